// round 1
// baseline (speedup 1.0000x reference)
#include <cuda_runtime.h>
#include <cuda_bf16.h>
#include <math.h>

// ---------------------------------------------------------------------------
// Problem constants (fixed by the reference setup)
// ---------------------------------------------------------------------------
#define S_LEN   2048
#define HID     4096
#define Q_LORA  1536
#define KV_LORA 512
#define KV_IN   576          // kv_lora + rope
#define NH      16
#define QK_NOPE 128
#define QK_ROPE 64
#define Q_HEAD  192          // QK_NOPE + QK_ROPE
#define V_DIM   128
#define QB_OUT  (NH * Q_HEAD)            // 3072
#define KVB_OUT (NH * (QK_NOPE + V_DIM)) // 4096
#define RMS_EPS 1e-6f
#define ROPE_BASE 10000.0f

// ---------------------------------------------------------------------------
// Static device scratch (allocation-free rule: __device__ globals)
// ---------------------------------------------------------------------------
__device__ float g_qlat_raw[S_LEN * Q_LORA];
__device__ float g_qlat    [S_LEN * Q_LORA];
__device__ float g_kv      [S_LEN * KV_IN];
__device__ float g_ckv     [S_LEN * KV_LORA];
__device__ float g_qfull   [S_LEN * QB_OUT];
__device__ float g_kvexp   [S_LEN * KVB_OUT];
__device__ float g_Q       [NH * S_LEN * Q_HEAD];
__device__ float g_K       [NH * S_LEN * Q_HEAD];
__device__ float g_V       [NH * S_LEN * V_DIM];
__device__ float g_scores  [(size_t)NH * S_LEN * S_LEN];   // 268 MB
__device__ float g_O       [NH * S_LEN * V_DIM];
__device__ float g_attn    [S_LEN * NH * V_DIM];

// ---------------------------------------------------------------------------
// SGEMM (TN): C[m,n] = alpha * sum_k A[m*K+k] * B[n*K+k]
// A row-major [M,K], B row-major [N,K]. 128x128x8 tile, 8x8 per thread.
// Batched via blockIdx.z with element strides.
// ---------------------------------------------------------------------------
__global__ __launch_bounds__(256)
void sgemm_tn(const float* __restrict__ A, const float* __restrict__ B,
              float* __restrict__ C, int M, int N, int K, float alpha,
              long long sA, long long sB, long long sC)
{
    A += (long long)blockIdx.z * sA;
    B += (long long)blockIdx.z * sB;
    C += (long long)blockIdx.z * sC;
    const int bm = blockIdx.y * 128;
    const int bn = blockIdx.x * 128;

    __shared__ float As[8][128];
    __shared__ float Bs[8][128];

    const int tid = threadIdx.x;
    const int tx = tid & 15;
    const int ty = tid >> 4;
    const int lr = tid >> 1;          // 0..127 row within tile
    const int lk = (tid & 1) * 4;     // 0 or 4

    float acc[8][8];
#pragma unroll
    for (int i = 0; i < 8; i++)
#pragma unroll
        for (int j = 0; j < 8; j++) acc[i][j] = 0.f;

    const bool aval = (bm + lr) < M;
    const bool bval = (bn + lr) < N;

    for (int k0 = 0; k0 < K; k0 += 8) {
        float4 a = aval ? *(const float4*)&A[(size_t)(bm + lr) * K + k0 + lk]
                        : make_float4(0.f, 0.f, 0.f, 0.f);
        float4 b = bval ? *(const float4*)&B[(size_t)(bn + lr) * K + k0 + lk]
                        : make_float4(0.f, 0.f, 0.f, 0.f);
        __syncthreads();
        As[lk + 0][lr] = a.x; As[lk + 1][lr] = a.y;
        As[lk + 2][lr] = a.z; As[lk + 3][lr] = a.w;
        Bs[lk + 0][lr] = b.x; Bs[lk + 1][lr] = b.y;
        Bs[lk + 2][lr] = b.z; Bs[lk + 3][lr] = b.w;
        __syncthreads();
#pragma unroll
        for (int kk = 0; kk < 8; kk++) {
            float ar[8], br[8];
#pragma unroll
            for (int i = 0; i < 8; i++) ar[i] = As[kk][ty * 8 + i];
#pragma unroll
            for (int j = 0; j < 8; j++) br[j] = Bs[kk][tx * 8 + j];
#pragma unroll
            for (int i = 0; i < 8; i++)
#pragma unroll
                for (int j = 0; j < 8; j++)
                    acc[i][j] = fmaf(ar[i], br[j], acc[i][j]);
        }
    }

#pragma unroll
    for (int i = 0; i < 8; i++) {
        int m = bm + ty * 8 + i;
        if (m < M) {
#pragma unroll
            for (int j = 0; j < 8; j++) {
                int n = bn + tx * 8 + j;
                if (n < N) C[(size_t)m * N + n] = alpha * acc[i][j];
            }
        }
    }
}

// ---------------------------------------------------------------------------
// SGEMM (NN): C[m,n] = alpha * sum_k A[m*K+k] * B[k*N+n]
// ---------------------------------------------------------------------------
__global__ __launch_bounds__(256)
void sgemm_nn(const float* __restrict__ A, const float* __restrict__ B,
              float* __restrict__ C, int M, int N, int K, float alpha,
              long long sA, long long sB, long long sC)
{
    A += (long long)blockIdx.z * sA;
    B += (long long)blockIdx.z * sB;
    C += (long long)blockIdx.z * sC;
    const int bm = blockIdx.y * 128;
    const int bn = blockIdx.x * 128;

    __shared__ float As[8][128];
    __shared__ float Bs[8][128];

    const int tid = threadIdx.x;
    const int tx = tid & 15;
    const int ty = tid >> 4;
    // A loader (same as TN)
    const int lr = tid >> 1;
    const int lk = (tid & 1) * 4;
    // B loader: row kk of the tile, 4 consecutive n
    const int bkk = tid >> 5;          // 0..7
    const int bn4 = (tid & 31) * 4;    // 0..124

    float acc[8][8];
#pragma unroll
    for (int i = 0; i < 8; i++)
#pragma unroll
        for (int j = 0; j < 8; j++) acc[i][j] = 0.f;

    const bool aval = (bm + lr) < M;
    const bool bval = (bn + bn4) < N;

    for (int k0 = 0; k0 < K; k0 += 8) {
        float4 a = aval ? *(const float4*)&A[(size_t)(bm + lr) * K + k0 + lk]
                        : make_float4(0.f, 0.f, 0.f, 0.f);
        float4 b = bval ? *(const float4*)&B[(size_t)(k0 + bkk) * N + bn + bn4]
                        : make_float4(0.f, 0.f, 0.f, 0.f);
        __syncthreads();
        As[lk + 0][lr] = a.x; As[lk + 1][lr] = a.y;
        As[lk + 2][lr] = a.z; As[lk + 3][lr] = a.w;
        *(float4*)&Bs[bkk][bn4] = b;
        __syncthreads();
#pragma unroll
        for (int kk = 0; kk < 8; kk++) {
            float ar[8], br[8];
#pragma unroll
            for (int i = 0; i < 8; i++) ar[i] = As[kk][ty * 8 + i];
#pragma unroll
            for (int j = 0; j < 8; j++) br[j] = Bs[kk][tx * 8 + j];
#pragma unroll
            for (int i = 0; i < 8; i++)
#pragma unroll
                for (int j = 0; j < 8; j++)
                    acc[i][j] = fmaf(ar[i], br[j], acc[i][j]);
        }
    }

#pragma unroll
    for (int i = 0; i < 8; i++) {
        int m = bm + ty * 8 + i;
        if (m < M) {
#pragma unroll
            for (int j = 0; j < 8; j++) {
                int n = bn + tx * 8 + j;
                if (n < N) C[(size_t)m * N + n] = alpha * acc[i][j];
            }
        }
    }
}

// ---------------------------------------------------------------------------
// RMSNorm: y = w * x * rsqrt(mean(x^2) + eps), one block per row
// ---------------------------------------------------------------------------
__global__ __launch_bounds__(256)
void rmsnorm_kernel(const float* __restrict__ x, const float* __restrict__ w,
                    float* __restrict__ y, int len, int xstride, int ystride)
{
    const int row = blockIdx.x;
    const float* xr = x + (size_t)row * xstride;
    float* yr = y + (size_t)row * ystride;

    float ss = 0.f;
    for (int j = threadIdx.x; j < len; j += 256) {
        float v = xr[j];
        ss += v * v;
    }
    __shared__ float red[256];
    red[threadIdx.x] = ss;
    __syncthreads();
    for (int s = 128; s > 0; s >>= 1) {
        if (threadIdx.x < s) red[threadIdx.x] += red[threadIdx.x + s];
        __syncthreads();
    }
    float inv = rsqrtf(red[0] / (float)len + RMS_EPS);
    for (int j = threadIdx.x; j < len; j += 256)
        yr[j] = w[j] * xr[j] * inv;
}

// ---------------------------------------------------------------------------
// RoPE helper (dim = 64, pairs of 32)
// ---------------------------------------------------------------------------
__device__ __forceinline__ void rope_cs(int pos, int jj, float& c, float& s)
{
    int i = jj & 31;                                  // frequency index
    float inv = __expf(-((float)(2 * i) / (float)QK_ROPE) * logf(ROPE_BASE));
    float ang = (float)pos * inv;
    c = cosf(ang);
    s = sinf(ang);
}

// Assemble Q[h][s][0:192] from g_qfull, applying RoPE on last 64 and folding
// the softmax scale.  grid(s=2048, h=16), block(192).
__global__ void assemble_q(float scale)
{
    const int s = blockIdx.x, h = blockIdx.y, j = threadIdx.x;
    const float* src = g_qfull + (size_t)s * QB_OUT + h * Q_HEAD;
    float v = src[j];
    if (j >= QK_NOPE) {
        int jj = j - QK_NOPE;
        float c, sn;
        rope_cs(s, jj, c, sn);
        float other = (jj < 32) ? -src[QK_NOPE + jj + 32] : src[QK_NOPE + jj - 32];
        v = v * c + other * sn;
    }
    g_Q[((size_t)h * S_LEN + s) * Q_HEAD + j] = v * scale;
}

// Assemble K[h][s][0:192]: k_nope from g_kvexp, k_pe (RoPE'd) broadcast.
__global__ void assemble_k()
{
    const int s = blockIdx.x, h = blockIdx.y, j = threadIdx.x;
    float v;
    if (j < QK_NOPE) {
        v = g_kvexp[(size_t)s * KVB_OUT + h * (QK_NOPE + V_DIM) + j];
    } else {
        int jj = j - QK_NOPE;
        const float* pe = g_kv + (size_t)s * KV_IN + KV_LORA;
        float c, sn;
        rope_cs(s, jj, c, sn);
        float other = (jj < 32) ? -pe[jj + 32] : pe[jj - 32];
        v = pe[jj] * c + other * sn;
    }
    g_K[((size_t)h * S_LEN + s) * Q_HEAD + j] = v;
}

// Assemble V[h][s][0:128]
__global__ void assemble_v()
{
    const int s = blockIdx.x, h = blockIdx.y, d = threadIdx.x;
    g_V[((size_t)h * S_LEN + s) * V_DIM + d] =
        g_kvexp[(size_t)s * KVB_OUT + h * (QK_NOPE + V_DIM) + QK_NOPE + d];
}

// ---------------------------------------------------------------------------
// Causal softmax in-place on g_scores. grid(q=2048, h=16), block(256).
// ---------------------------------------------------------------------------
__global__ __launch_bounds__(256)
void softmax_causal()
{
    const int q = blockIdx.x, h = blockIdx.y;
    float* row = g_scores + ((size_t)h * S_LEN + q) * S_LEN;
    const int L = q + 1;

    __shared__ float red[256];

    float m = -1e30f;
    for (int j = threadIdx.x; j < L; j += 256) m = fmaxf(m, row[j]);
    red[threadIdx.x] = m;
    __syncthreads();
    for (int s = 128; s > 0; s >>= 1) {
        if (threadIdx.x < s)
            red[threadIdx.x] = fmaxf(red[threadIdx.x], red[threadIdx.x + s]);
        __syncthreads();
    }
    m = red[0];
    __syncthreads();

    float sum = 0.f;
    for (int j = threadIdx.x; j < L; j += 256) sum += expf(row[j] - m);
    red[threadIdx.x] = sum;
    __syncthreads();
    for (int s = 128; s > 0; s >>= 1) {
        if (threadIdx.x < s) red[threadIdx.x] += red[threadIdx.x + s];
        __syncthreads();
    }
    float invs = 1.f / red[0];

    for (int j = threadIdx.x; j < L; j += 256)
        row[j] = expf(row[j] - m) * invs;
    for (int j = L + threadIdx.x; j < S_LEN; j += 256)
        row[j] = 0.f;
}

// attn_flat[s, h*128+d] = O[h][s][d]
__global__ void transpose_attn()
{
    const int s = blockIdx.x, h = blockIdx.y, d = threadIdx.x;
    g_attn[(size_t)s * (NH * V_DIM) + h * V_DIM + d] =
        g_O[((size_t)h * S_LEN + s) * V_DIM + d];
}

// ---------------------------------------------------------------------------
// Host launch
// ---------------------------------------------------------------------------
extern "C" void kernel_launch(void* const* d_in, const int* in_sizes, int n_in,
                              void* d_out, int out_size)
{
    (void)in_sizes; (void)n_in; (void)out_size;
    const float* hidden = (const float*)d_in[0];
    // d_in[1] = position_ids (arange; positions == row index, used implicitly)
    const float* wq_a   = (const float*)d_in[2];
    const float* qnw    = (const float*)d_in[3];
    const float* wq_b   = (const float*)d_in[4];
    const float* wkv_a  = (const float*)d_in[5];
    const float* kvnw   = (const float*)d_in[6];
    const float* wkv_b  = (const float*)d_in[7];
    const float* wo     = (const float*)d_in[8];
    float* out = (float*)d_out;

    float *qlat_raw, *qlat, *kv, *ckv, *qfull, *kvexp, *Q, *K, *V, *scores, *O, *attn;
    cudaGetSymbolAddress((void**)&qlat_raw, g_qlat_raw);
    cudaGetSymbolAddress((void**)&qlat,     g_qlat);
    cudaGetSymbolAddress((void**)&kv,       g_kv);
    cudaGetSymbolAddress((void**)&ckv,      g_ckv);
    cudaGetSymbolAddress((void**)&qfull,    g_qfull);
    cudaGetSymbolAddress((void**)&kvexp,    g_kvexp);
    cudaGetSymbolAddress((void**)&Q,        g_Q);
    cudaGetSymbolAddress((void**)&K,        g_K);
    cudaGetSymbolAddress((void**)&V,        g_V);
    cudaGetSymbolAddress((void**)&scores,   g_scores);
    cudaGetSymbolAddress((void**)&O,        g_O);
    cudaGetSymbolAddress((void**)&attn,     g_attn);

    const float softmax_scale = rsqrtf((float)Q_HEAD);

    dim3 blk(256);

    // 1. q_lat_raw = hidden @ wq_a^T   [2048,1536]
    sgemm_tn<<<dim3(Q_LORA / 128, S_LEN / 128, 1), blk>>>(
        hidden, wq_a, qlat_raw, S_LEN, Q_LORA, HID, 1.f, 0, 0, 0);
    // 2. kv = hidden @ wkv_a^T         [2048,576]
    sgemm_tn<<<dim3((KV_IN + 127) / 128, S_LEN / 128, 1), blk>>>(
        hidden, wkv_a, kv, S_LEN, KV_IN, HID, 1.f, 0, 0, 0);
    // 3. RMSNorm(q_lat)
    rmsnorm_kernel<<<S_LEN, 256>>>(qlat_raw, qnw, qlat, Q_LORA, Q_LORA, Q_LORA);
    // 4. RMSNorm(compressed_kv)
    rmsnorm_kernel<<<S_LEN, 256>>>(kv, kvnw, ckv, KV_LORA, KV_IN, KV_LORA);
    // 5. q = q_lat @ wq_b^T            [2048,3072]
    sgemm_tn<<<dim3(QB_OUT / 128, S_LEN / 128, 1), blk>>>(
        qlat, wq_b, qfull, S_LEN, QB_OUT, Q_LORA, 1.f, 0, 0, 0);
    // 6. kv_exp = ckv @ wkv_b^T        [2048,4096]
    sgemm_tn<<<dim3(KVB_OUT / 128, S_LEN / 128, 1), blk>>>(
        ckv, wkv_b, kvexp, S_LEN, KVB_OUT, KV_LORA, 1.f, 0, 0, 0);
    // 7-9. assemble head-major Q (RoPE+scale), K (RoPE pe), V
    assemble_q<<<dim3(S_LEN, NH), Q_HEAD>>>(softmax_scale);
    assemble_k<<<dim3(S_LEN, NH), Q_HEAD>>>();
    assemble_v<<<dim3(S_LEN, NH), V_DIM>>>();
    // 10. scores[h] = Q[h] @ K[h]^T (scale pre-folded)
    sgemm_tn<<<dim3(S_LEN / 128, S_LEN / 128, NH), blk>>>(
        Q, K, scores, S_LEN, S_LEN, Q_HEAD, 1.f,
        (long long)S_LEN * Q_HEAD, (long long)S_LEN * Q_HEAD,
        (long long)S_LEN * S_LEN);
    // 11. causal softmax in place
    softmax_causal<<<dim3(S_LEN, NH), 256>>>();
    // 12. O[h] = P[h] @ V[h]
    sgemm_nn<<<dim3(V_DIM / 128, S_LEN / 128, NH), blk>>>(
        scores, V, O, S_LEN, V_DIM, S_LEN, 1.f,
        (long long)S_LEN * S_LEN, (long long)S_LEN * V_DIM,
        (long long)S_LEN * V_DIM);
    // 13. flatten heads
    transpose_attn<<<dim3(S_LEN, NH), V_DIM>>>();
    // 14. out = attn @ wo^T            [2048,4096]
    sgemm_tn<<<dim3(HID / 128, S_LEN / 128, 1), blk>>>(
        attn, wo, out, S_LEN, HID, NH * V_DIM, 1.f, 0, 0, 0);
}

// round 2
// speedup vs baseline: 2.3333x; 2.3333x over previous
#include <cuda_runtime.h>
#include <cuda_bf16.h>
#include <math.h>
#include <stdint.h>

// ---------------------------------------------------------------------------
// Problem constants
// ---------------------------------------------------------------------------
#define S_LEN   2048
#define HID     4096
#define Q_LORA  1536
#define KV_LORA 512
#define KV_IN   576
#define NH      16
#define QK_NOPE 128
#define QK_ROPE 64
#define Q_HEAD  192
#define V_DIM   128
#define QB_OUT  (NH * Q_HEAD)            // 3072
#define KVB_OUT (NH * (QK_NOPE + V_DIM)) // 4096
#define RMS_EPS 1e-6f
#define ROPE_BASE 10000.0f

typedef __nv_bfloat16 bf16;

// ---------------------------------------------------------------------------
// Static device scratch
// fp32 intermediates
// ---------------------------------------------------------------------------
__device__ float g_qlat_raw[S_LEN * Q_LORA];
__device__ float g_kv      [S_LEN * KV_IN];
__device__ float g_qfull   [S_LEN * QB_OUT];
__device__ float g_kvexp   [S_LEN * KVB_OUT];
__device__ float g_scores  [(size_t)NH * S_LEN * S_LEN];
__device__ float g_O       [NH * S_LEN * V_DIM];

// bf16 split-3 operands (K dimension tripled). A-side = [hi|lo|hi], B-side = [hi|hi|lo]
__device__ bf16 g_hidden3 [(size_t)S_LEN * 3 * HID];
__device__ bf16 g_wqa3    [(size_t)Q_LORA * 3 * HID];
__device__ bf16 g_wkva3   [(size_t)KV_IN * 3 * HID];
__device__ bf16 g_qlat3   [(size_t)S_LEN * 3 * Q_LORA];
__device__ bf16 g_wqb3    [(size_t)QB_OUT * 3 * Q_LORA];
__device__ bf16 g_ckv3    [(size_t)S_LEN * 3 * KV_LORA];
__device__ bf16 g_wkvb3   [(size_t)KVB_OUT * 3 * KV_LORA];
__device__ bf16 g_Q3      [(size_t)NH * S_LEN * 3 * Q_HEAD];
__device__ bf16 g_K3      [(size_t)NH * S_LEN * 3 * Q_HEAD];
__device__ bf16 g_Vt3     [(size_t)NH * V_DIM * 3 * S_LEN];
__device__ bf16 g_P3      [(size_t)NH * S_LEN * 3 * S_LEN];
__device__ bf16 g_attn3   [(size_t)S_LEN * 3 * (NH * V_DIM)];
__device__ bf16 g_wo3     [(size_t)HID * 3 * (NH * V_DIM)];

// ---------------------------------------------------------------------------
// helpers
// ---------------------------------------------------------------------------
__device__ __forceinline__ uint32_t smem_u32(const void* p) {
    return (uint32_t)__cvta_generic_to_shared(p);
}

__device__ __forceinline__ void ldsm_x4(uint32_t& r0, uint32_t& r1,
                                        uint32_t& r2, uint32_t& r3, uint32_t addr) {
    asm volatile("ldmatrix.sync.aligned.m8n8.x4.shared.b16 {%0,%1,%2,%3}, [%4];"
                 : "=r"(r0), "=r"(r1), "=r"(r2), "=r"(r3) : "r"(addr));
}
__device__ __forceinline__ void ldsm_x2(uint32_t& r0, uint32_t& r1, uint32_t addr) {
    asm volatile("ldmatrix.sync.aligned.m8n8.x2.shared.b16 {%0,%1}, [%2];"
                 : "=r"(r0), "=r"(r1) : "r"(addr));
}
__device__ __forceinline__ void mma16816(float* c, const uint32_t* a, const uint32_t* b) {
    asm volatile("mma.sync.aligned.m16n8k16.row.col.f32.bf16.bf16.f32 "
                 "{%0,%1,%2,%3}, {%4,%5,%6,%7}, {%8,%9}, {%0,%1,%2,%3};"
                 : "+f"(c[0]), "+f"(c[1]), "+f"(c[2]), "+f"(c[3])
                 : "r"(a[0]), "r"(a[1]), "r"(a[2]), "r"(a[3]),
                   "r"(b[0]), "r"(b[1]));
}

__device__ __forceinline__ void split2(float v, bf16& h, bf16& l) {
    h = __float2bfloat16(v);
    l = __float2bfloat16(v - __bfloat162float(h));
}

// ---------------------------------------------------------------------------
// bf16 TN GEMM: C[m,n] = sum_k A[m,k]*B[n,k], A [M,K] bf16, B [N,K] bf16,
// C fp32 [M,N]. K multiple of 32, M multiple of 128. N guarded.
// CTA tile 128x128x32, 8 warps (2x4), warp tile 64x32, mma m16n8k16.
// ---------------------------------------------------------------------------
#define GBM 128
#define GBK 32
#define SMPAD 40   // row stride in halves (conflict-free, 16B-aligned)

__global__ __launch_bounds__(256)
void gemm_bf16_tn(const bf16* __restrict__ A, const bf16* __restrict__ B,
                  float* __restrict__ C, int M, int N, int K,
                  long long sA, long long sB, long long sC, int causal)
{
    const int bm = blockIdx.y * GBM;
    const int bn = blockIdx.x * GBM;
    if (causal && bn > bm + GBM - 1) return;   // dead causal block

    A += (long long)blockIdx.z * sA;
    B += (long long)blockIdx.z * sB;
    C += (long long)blockIdx.z * sC;

    __shared__ bf16 As[2][GBM][SMPAD];
    __shared__ bf16 Bs[2][GBM][SMPAD];

    const int tid  = threadIdx.x;
    const int lane = tid & 31;
    const int wid  = tid >> 5;
    const int wm   = (wid >> 2) * 64;   // warp m offset (0,64)
    const int wn   = (wid & 3) * 32;    // warp n offset (0..96)
    const int gid  = lane >> 2;
    const int tig  = lane & 3;

    // global loader mapping: 512 16B-vectors per operand per tile, 2 per thread
    const int lr = tid >> 2;            // 0..63
    const int lc = (tid & 3) * 8;       // 0,8,16,24

    float acc[4][4][4];
#pragma unroll
    for (int a = 0; a < 4; a++)
#pragma unroll
        for (int b = 0; b < 4; b++)
#pragma unroll
            for (int c = 0; c < 4; c++) acc[a][b][c] = 0.f;

    const int ntiles = K / GBK;

    uint4 av0, av1, bv0, bv1;
    auto glob_load = [&](int kt) {
        const int k0 = kt * GBK;
        const bf16* Ap = A + (size_t)(bm + lr) * K + k0 + lc;
        av0 = *(const uint4*)Ap;
        av1 = *(const uint4*)(Ap + (size_t)64 * K);
        const int n0 = bn + lr;
        const bf16* Bp = B + (size_t)n0 * K + k0 + lc;
        bv0 = (n0      < N) ? *(const uint4*)Bp                   : make_uint4(0,0,0,0);
        bv1 = (n0 + 64 < N) ? *(const uint4*)(Bp + (size_t)64 * K) : make_uint4(0,0,0,0);
    };
    auto sts = [&](int buf) {
        *(uint4*)&As[buf][lr     ][lc] = av0;
        *(uint4*)&As[buf][lr + 64][lc] = av1;
        *(uint4*)&Bs[buf][lr     ][lc] = bv0;
        *(uint4*)&Bs[buf][lr + 64][lc] = bv1;
    };

    const uint32_t as_base = smem_u32(&As[0][0][0]);
    const uint32_t bs_base = smem_u32(&Bs[0][0][0]);
    const uint32_t BUFB = GBM * SMPAD * 2;   // bytes per buffer

    const int a_row = wm + (lane & 15);
    const int a_col = (lane >> 4) * 8;
    const int b_row = wn + (lane & 7);
    const int b_col = ((lane >> 3) & 1) * 8;

    auto compute = [&](int buf) {
#pragma unroll
        for (int ks = 0; ks < 2; ks++) {
            uint32_t af[4][4], bfr[4][2];
#pragma unroll
            for (int mt = 0; mt < 4; mt++) {
                uint32_t addr = as_base + buf * BUFB +
                    (uint32_t)(((a_row + mt * 16) * SMPAD + ks * 16 + a_col) * 2);
                ldsm_x4(af[mt][0], af[mt][1], af[mt][2], af[mt][3], addr);
            }
#pragma unroll
            for (int nt = 0; nt < 4; nt++) {
                uint32_t addr = bs_base + buf * BUFB +
                    (uint32_t)(((b_row + nt * 8) * SMPAD + ks * 16 + b_col) * 2);
                ldsm_x2(bfr[nt][0], bfr[nt][1], addr);
            }
#pragma unroll
            for (int mt = 0; mt < 4; mt++)
#pragma unroll
                for (int nt = 0; nt < 4; nt++)
                    mma16816(acc[mt][nt], af[mt], bfr[nt]);
        }
    };

    glob_load(0);
    sts(0);
    __syncthreads();
    int buf = 0;
    for (int kt = 0; kt < ntiles; kt++) {
        if (kt + 1 < ntiles) glob_load(kt + 1);
        compute(buf);
        if (kt + 1 < ntiles) {
            sts(buf ^ 1);
            __syncthreads();
            buf ^= 1;
        }
    }

    // epilogue
#pragma unroll
    for (int mt = 0; mt < 4; mt++) {
        const int row = bm + wm + mt * 16 + gid;
#pragma unroll
        for (int nt = 0; nt < 4; nt++) {
            const int col = bn + wn + nt * 8 + tig * 2;
            if (col < N) {
                float2 v0 = make_float2(acc[mt][nt][0], acc[mt][nt][1]);
                float2 v1 = make_float2(acc[mt][nt][2], acc[mt][nt][3]);
                *(float2*)&C[(size_t)row * N + col]       = v0;
                *(float2*)&C[(size_t)(row + 8) * N + col] = v1;
            }
        }
    }
}

// ---------------------------------------------------------------------------
// fp32 -> bf16 split-3 (aside=1: [hi|lo|hi], aside=0: [hi|hi|lo])
// ---------------------------------------------------------------------------
__global__ __launch_bounds__(256)
void split3_kernel(const float* __restrict__ x, bf16* __restrict__ y,
                   long long R, long long C, int aside)
{
    const long long n = R * C;
    for (long long i = (long long)blockIdx.x * blockDim.x + threadIdx.x; i < n;
         i += (long long)gridDim.x * blockDim.x) {
        long long r = i / C, c = i - r * C;
        bf16 h, l;
        split2(x[i], h, l);
        bf16* row = y + r * 3 * C;
        row[c]         = h;
        row[C + c]     = aside ? l : h;
        row[2 * C + c] = aside ? h : l;
    }
}

// ---------------------------------------------------------------------------
// RMSNorm fused with A-side split-3 output
// ---------------------------------------------------------------------------
__global__ __launch_bounds__(256)
void rmsnorm_split(const float* __restrict__ x, const float* __restrict__ w,
                   bf16* __restrict__ y3, int len, int xstride)
{
    const int row = blockIdx.x;
    const float* xr = x + (size_t)row * xstride;
    bf16* yr = y3 + (size_t)row * 3 * len;

    float ss = 0.f;
    for (int j = threadIdx.x; j < len; j += 256) { float v = xr[j]; ss += v * v; }
    __shared__ float red[256];
    red[threadIdx.x] = ss;
    __syncthreads();
    for (int s = 128; s > 0; s >>= 1) {
        if (threadIdx.x < s) red[threadIdx.x] += red[threadIdx.x + s];
        __syncthreads();
    }
    const float inv = rsqrtf(red[0] / (float)len + RMS_EPS);
    for (int j = threadIdx.x; j < len; j += 256) {
        bf16 h, l;
        split2(w[j] * xr[j] * inv, h, l);
        yr[j] = h; yr[len + j] = l; yr[2 * len + j] = h;
    }
}

// ---------------------------------------------------------------------------
// RoPE helper
// ---------------------------------------------------------------------------
__device__ __forceinline__ void rope_cs(int pos, int jj, float& c, float& s)
{
    int i = jj & 31;
    float inv = __expf(-((float)(2 * i) / (float)QK_ROPE) * logf(ROPE_BASE));
    float ang = (float)pos * inv;
    c = cosf(ang);
    s = sinf(ang);
}

// Q assemble: RoPE + softmax scale, A-side split. grid(s, h), block(192)
__global__ void assemble_q(float scale)
{
    const int s = blockIdx.x, h = blockIdx.y, j = threadIdx.x;
    const float* src = g_qfull + (size_t)s * QB_OUT + h * Q_HEAD;
    float v = src[j];
    if (j >= QK_NOPE) {
        int jj = j - QK_NOPE;
        float c, sn;
        rope_cs(s, jj, c, sn);
        float other = (jj < 32) ? -src[QK_NOPE + jj + 32] : src[QK_NOPE + jj - 32];
        v = v * c + other * sn;
    }
    v *= scale;
    bf16 hh, ll;
    split2(v, hh, ll);
    bf16* dst = g_Q3 + ((size_t)h * S_LEN + s) * 3 * Q_HEAD;
    dst[j] = hh; dst[Q_HEAD + j] = ll; dst[2 * Q_HEAD + j] = hh;
}

// K assemble: B-side split. grid(s, h), block(192)
__global__ void assemble_k()
{
    const int s = blockIdx.x, h = blockIdx.y, j = threadIdx.x;
    float v;
    if (j < QK_NOPE) {
        v = g_kvexp[(size_t)s * KVB_OUT + h * (QK_NOPE + V_DIM) + j];
    } else {
        int jj = j - QK_NOPE;
        const float* pe = g_kv + (size_t)s * KV_IN + KV_LORA;
        float c, sn;
        rope_cs(s, jj, c, sn);
        float other = (jj < 32) ? -pe[jj + 32] : pe[jj - 32];
        v = pe[jj] * c + other * sn;
    }
    bf16 hh, ll;
    split2(v, hh, ll);
    bf16* dst = g_K3 + ((size_t)h * S_LEN + s) * 3 * Q_HEAD;
    dst[j] = hh; dst[Q_HEAD + j] = hh; dst[2 * Q_HEAD + j] = ll;
}

// V transpose + B-side split into Vt3[h][d][3*S]. 32x32 smem transpose.
// grid(x = s_tile(64), y = d_tile(4), z = h), block(32,32)
__global__ void assemble_vt()
{
    __shared__ float sm[32][33];
    const int h = blockIdx.z;
    const int s0 = blockIdx.x * 32, d0 = blockIdx.y * 32;
    const int tx = threadIdx.x, ty = threadIdx.y;
    sm[ty][tx] = g_kvexp[(size_t)(s0 + ty) * KVB_OUT +
                         h * (QK_NOPE + V_DIM) + QK_NOPE + d0 + tx];
    __syncthreads();
    const int d = d0 + ty, s = s0 + tx;
    bf16 hh, ll;
    split2(sm[tx][ty], hh, ll);
    bf16* dst = g_Vt3 + ((size_t)h * V_DIM + d) * 3 * S_LEN;
    dst[s] = hh; dst[S_LEN + s] = hh; dst[2 * S_LEN + s] = ll;
}

// ---------------------------------------------------------------------------
// Causal softmax reading fp32 scores, writing A-side split P3.
// grid(q, h), block(256)
// ---------------------------------------------------------------------------
__global__ __launch_bounds__(256)
void softmax_split()
{
    const int q = blockIdx.x, h = blockIdx.y;
    const float* row = g_scores + ((size_t)h * S_LEN + q) * S_LEN;
    bf16* prow = g_P3 + ((size_t)h * S_LEN + q) * 3 * S_LEN;
    const int L = q + 1;

    __shared__ float red[256];

    float m = -1e30f;
    for (int j = threadIdx.x; j < L; j += 256) m = fmaxf(m, row[j]);
    red[threadIdx.x] = m;
    __syncthreads();
    for (int s = 128; s > 0; s >>= 1) {
        if (threadIdx.x < s)
            red[threadIdx.x] = fmaxf(red[threadIdx.x], red[threadIdx.x + s]);
        __syncthreads();
    }
    m = red[0];
    __syncthreads();

    float sum = 0.f;
    for (int j = threadIdx.x; j < L; j += 256) sum += expf(row[j] - m);
    red[threadIdx.x] = sum;
    __syncthreads();
    for (int s = 128; s > 0; s >>= 1) {
        if (threadIdx.x < s) red[threadIdx.x] += red[threadIdx.x + s];
        __syncthreads();
    }
    const float invs = 1.f / red[0];

    for (int j = threadIdx.x; j < L; j += 256) {
        bf16 hh, ll;
        split2(expf(row[j] - m) * invs, hh, ll);
        prow[j] = hh; prow[S_LEN + j] = ll; prow[2 * S_LEN + j] = hh;
    }
    bf16 z = __float2bfloat16(0.f);
    for (int j = L + threadIdx.x; j < S_LEN; j += 256) {
        prow[j] = z; prow[S_LEN + j] = z; prow[2 * S_LEN + j] = z;
    }
}

// attn3[s][3*2048] A-side split from O[h][s][d]. grid(s, h), block(128)
__global__ void transpose_attn_split()
{
    const int s = blockIdx.x, h = blockIdx.y, d = threadIdx.x;
    float v = g_O[((size_t)h * S_LEN + s) * V_DIM + d];
    bf16 hh, ll;
    split2(v, hh, ll);
    bf16* dst = g_attn3 + (size_t)s * 3 * (NH * V_DIM);
    const int c = h * V_DIM + d;
    dst[c] = hh;
    dst[NH * V_DIM + c] = ll;
    dst[2 * NH * V_DIM + c] = hh;
}

// ---------------------------------------------------------------------------
// Host launch
// ---------------------------------------------------------------------------
extern "C" void kernel_launch(void* const* d_in, const int* in_sizes, int n_in,
                              void* d_out, int out_size)
{
    (void)in_sizes; (void)n_in; (void)out_size;
    const float* hidden = (const float*)d_in[0];
    const float* wq_a   = (const float*)d_in[2];
    const float* qnw    = (const float*)d_in[3];
    const float* wq_b   = (const float*)d_in[4];
    const float* wkv_a  = (const float*)d_in[5];
    const float* kvnw   = (const float*)d_in[6];
    const float* wkv_b  = (const float*)d_in[7];
    const float* wo     = (const float*)d_in[8];
    float* out = (float*)d_out;

    float *qlat_raw, *kv, *qfull, *kvexp, *scores, *O;
    bf16 *hidden3, *wqa3, *wkva3, *qlat3, *wqb3, *ckv3, *wkvb3;
    bf16 *Q3, *K3, *Vt3, *P3, *attn3, *wo3;
    cudaGetSymbolAddress((void**)&qlat_raw, g_qlat_raw);
    cudaGetSymbolAddress((void**)&kv,       g_kv);
    cudaGetSymbolAddress((void**)&qfull,    g_qfull);
    cudaGetSymbolAddress((void**)&kvexp,    g_kvexp);
    cudaGetSymbolAddress((void**)&scores,   g_scores);
    cudaGetSymbolAddress((void**)&O,        g_O);
    cudaGetSymbolAddress((void**)&hidden3,  g_hidden3);
    cudaGetSymbolAddress((void**)&wqa3,     g_wqa3);
    cudaGetSymbolAddress((void**)&wkva3,    g_wkva3);
    cudaGetSymbolAddress((void**)&qlat3,    g_qlat3);
    cudaGetSymbolAddress((void**)&wqb3,     g_wqb3);
    cudaGetSymbolAddress((void**)&ckv3,     g_ckv3);
    cudaGetSymbolAddress((void**)&wkvb3,    g_wkvb3);
    cudaGetSymbolAddress((void**)&Q3,       g_Q3);
    cudaGetSymbolAddress((void**)&K3,       g_K3);
    cudaGetSymbolAddress((void**)&Vt3,      g_Vt3);
    cudaGetSymbolAddress((void**)&P3,       g_P3);
    cudaGetSymbolAddress((void**)&attn3,    g_attn3);
    cudaGetSymbolAddress((void**)&wo3,      g_wo3);

    const float softmax_scale = rsqrtf((float)Q_HEAD);
    dim3 blk(256);

    // splits of inputs / weights
    split3_kernel<<<1024, 256>>>(hidden, hidden3, S_LEN, HID, 1);
    split3_kernel<<<1024, 256>>>(wq_a,  wqa3,  Q_LORA,  HID, 0);
    split3_kernel<<<1024, 256>>>(wkv_a, wkva3, KV_IN,   HID, 0);
    split3_kernel<<<1024, 256>>>(wq_b,  wqb3,  QB_OUT,  Q_LORA, 0);
    split3_kernel<<<1024, 256>>>(wkv_b, wkvb3, KVB_OUT, KV_LORA, 0);
    split3_kernel<<<1024, 256>>>(wo,    wo3,   HID,     NH * V_DIM, 0);

    // 1. q_lat_raw = hidden @ wq_a^T
    gemm_bf16_tn<<<dim3(Q_LORA / 128, S_LEN / 128, 1), blk>>>(
        hidden3, wqa3, qlat_raw, S_LEN, Q_LORA, 3 * HID, 0, 0, 0, 0);
    // 2. kv = hidden @ wkv_a^T  (N=576, guarded)
    gemm_bf16_tn<<<dim3((KV_IN + 127) / 128, S_LEN / 128, 1), blk>>>(
        hidden3, wkva3, kv, S_LEN, KV_IN, 3 * HID, 0, 0, 0, 0);
    // 3-4. RMSNorms with fused split
    rmsnorm_split<<<S_LEN, 256>>>(qlat_raw, qnw, qlat3, Q_LORA, Q_LORA);
    rmsnorm_split<<<S_LEN, 256>>>(kv, kvnw, ckv3, KV_LORA, KV_IN);
    // 5. q = q_lat @ wq_b^T
    gemm_bf16_tn<<<dim3(QB_OUT / 128, S_LEN / 128, 1), blk>>>(
        qlat3, wqb3, qfull, S_LEN, QB_OUT, 3 * Q_LORA, 0, 0, 0, 0);
    // 6. kv_exp = ckv @ wkv_b^T
    gemm_bf16_tn<<<dim3(KVB_OUT / 128, S_LEN / 128, 1), blk>>>(
        ckv3, wkvb3, kvexp, S_LEN, KVB_OUT, 3 * KV_LORA, 0, 0, 0, 0);
    // 7-9. assemble split operands
    assemble_q<<<dim3(S_LEN, NH), Q_HEAD>>>(softmax_scale);
    assemble_k<<<dim3(S_LEN, NH), Q_HEAD>>>();
    assemble_vt<<<dim3(S_LEN / 32, V_DIM / 32, NH), dim3(32, 32)>>>();
    // 10. scores = Q @ K^T (causal blocks skipped)
    gemm_bf16_tn<<<dim3(S_LEN / 128, S_LEN / 128, NH), blk>>>(
        Q3, K3, scores, S_LEN, S_LEN, 3 * Q_HEAD,
        (long long)S_LEN * 3 * Q_HEAD, (long long)S_LEN * 3 * Q_HEAD,
        (long long)S_LEN * S_LEN, 1);
    // 11. causal softmax + split
    softmax_split<<<dim3(S_LEN, NH), 256>>>();
    // 12. O = P @ V
    gemm_bf16_tn<<<dim3(V_DIM / 128, S_LEN / 128, NH), blk>>>(
        P3, Vt3, O, S_LEN, V_DIM, 3 * S_LEN,
        (long long)S_LEN * 3 * S_LEN, (long long)V_DIM * 3 * S_LEN,
        (long long)S_LEN * V_DIM, 0);
    // 13. flatten heads + split
    transpose_attn_split<<<dim3(S_LEN, NH), V_DIM>>>();
    // 14. out = attn @ wo^T
    gemm_bf16_tn<<<dim3(HID / 128, S_LEN / 128, 1), blk>>>(
        attn3, wo3, out, S_LEN, HID, 3 * NH * V_DIM, 0, 0, 0, 0);
}